// round 10
// baseline (speedup 1.0000x reference)
#include <cuda_runtime.h>
#include <math.h>
#include <stdint.h>

#define Bn 1024
#define En 512
#define Nn 1024
#define Mn 64
#define Pn 70
#define EPSf 1e-16f

#define NSPLIT 4
#define BSPLIT (Bn / NSPLIT)   // 256

// scratch: z[B,N]; proj partials g_pp[b][chunk8][72]
__device__ float g_z[Bn * Nn];
__device__ float g_pp[Bn * 8 * 72];

__device__ __forceinline__ float softplusf(float x) {
    return fmaxf(x, 0.0f) + log1pf(expf(-fabsf(x)));
}
__device__ __forceinline__ uint32_t s2u(const void* p) {
    return (uint32_t)__cvta_generic_to_shared(p);
}
__device__ __forceinline__ void mbar_init(uint32_t a, uint32_t cnt) {
    asm volatile("mbarrier.init.shared.b64 [%0], %1;" :: "r"(a), "r"(cnt) : "memory");
}
__device__ __forceinline__ void mbar_expect_tx(uint32_t a, uint32_t bytes) {
    asm volatile("mbarrier.arrive.expect_tx.shared.b64 _, [%0], %1;" :: "r"(a), "r"(bytes) : "memory");
}
__device__ __forceinline__ void mbar_arrive(uint32_t a) {
    asm volatile("mbarrier.arrive.shared.b64 _, [%0];" :: "r"(a) : "memory");
}
__device__ __forceinline__ void bulk_g2s(uint32_t dst, const void* src, uint32_t bytes, uint32_t mbar) {
    asm volatile("cp.async.bulk.shared::cta.global.mbarrier::complete_tx::bytes [%0], [%1], %2, [%3];"
                 :: "r"(dst), "l"(src), "r"(bytes), "r"(mbar) : "memory");
}
__device__ __forceinline__ void mbar_wait(uint32_t a, uint32_t parity) {
    asm volatile(
        "{\n\t.reg .pred P;\n\t"
        "W0_%=:\n\t"
        "mbarrier.try_wait.parity.acquire.cta.shared::cta.b64 P, [%0], %1, 0x989680;\n\t"
        "@P bra.uni W1_%=;\n\t"
        "bra.uni W0_%=;\n\t"
        "W1_%=:\n\t}"
        :: "r"(a), "r"(parity) : "memory");
}

// ===================== K1: proj partials, 8-way split-K (E chunks of 64) ==========
// 1024 CTAs: group g = bx>>3 owns batch rows 8g..8g+7; chunk = bx&7 owns E range [64*chunk, +64)
__global__ __launch_bounds__(576) void proj_kernel(const float* __restrict__ emb,
                                                   const float* __restrict__ W,
                                                   const float* __restrict__ bias) {
    __shared__ float W_sh[64 * Pn];    // 17920 B
    __shared__ float e_sh[8 * 64];     // 2048 B

    const int tid   = threadIdx.x;
    const int group = blockIdx.x >> 3;
    const int chunk = blockIdx.x & 7;
    const int b0    = group * 8;
    const int e0    = chunk * 64;

    {
        const float4* Wv = (const float4*)(W + (size_t)e0 * Pn);   // 64*70*chunk divisible by 4
        float4* Ws = (float4*)W_sh;
        #pragma unroll 2
        for (int i = tid; i < 64 * Pn / 4; i += 576) Ws[i] = Wv[i];
        if (tid < 128) {   // 8 rows x 16 float4
            int r = tid >> 4, j = tid & 15;
            ((float4*)(e_sh + r * 64))[j] =
                ((const float4*)(emb + (size_t)(b0 + r) * En + e0))[j];
        }
    }
    __syncthreads();

    if (tid < 560) {
        const int r = tid / 70, c = tid - r * 70;
        const float* er = e_sh + r * 64;
        float a0 = 0.f, a1 = 0.f, a2 = 0.f, a3 = 0.f;
        #pragma unroll 8
        for (int e = 0; e < 64; e += 4) {
            float4 ev = *(const float4*)(er + e);
            a0 = fmaf(ev.x, W_sh[(e + 0) * Pn + c], a0);
            a1 = fmaf(ev.y, W_sh[(e + 1) * Pn + c], a1);
            a2 = fmaf(ev.z, W_sh[(e + 2) * Pn + c], a2);
            a3 = fmaf(ev.w, W_sh[(e + 3) * Pn + c], a3);
        }
        float acc = (a0 + a1) + (a2 + a3);
        if (chunk == 0) acc += bias[c];
        g_pp[((size_t)(b0 + r) * 8 + chunk) * 72 + c] = acc;
    }
}

__device__ __forceinline__ float pp_sum(int b, int i) {
    const float* p = g_pp + (size_t)b * 8 * 72 + i;
    float s = 0.f;
    #pragma unroll
    for (int c = 0; c < 8; ++c) s += p[c * 72];
    return s;
}

// ===================== K2: z = beta * cos-sim — pure stream =====================
#define K2_TB 16384
#define K2_SMEM_BYTES (4 * K2_TB + 80 * 4 + 12 * 8)

__global__ __launch_bounds__(256) void sim_kernel(const float* __restrict__ memory, int base_b) {
    extern __shared__ float smem[];
    float*    tiles = smem;                       // 16384 floats (4 x 16KB)
    float*    k_sh  = smem + 16384;               // 64
    float*    red   = k_sh + 64;                  // 2
    float*    ps    = red + 2;                    // 1
    uint64_t* mbars = (uint64_t*)(k_sh + 80);     // full[0..7], empty[8..11]

    const int b    = base_b + (blockIdx.x >> 1);
    const int half = blockIdx.x & 1;
    const int tid  = threadIdx.x;
    const int lane = tid & 31;
    const int wid  = tid >> 5;
    const float* mb = memory + ((size_t)b * Nn + half * 512) * Mn;

    const uint32_t tiles_u = s2u(tiles);
    const uint32_t mbar0   = s2u(mbars);

    if (tid == 0) {
        #pragma unroll
        for (int t = 0; t < 8; ++t) mbar_init(mbar0 + 8u * t, 1);
        #pragma unroll
        for (int k = 0; k < 4; ++k) mbar_init(mbar0 + 8u * (8 + k), 32);
    }
    if (tid < 64) {
        float v = pp_sum(b, tid);
        k_sh[tid] = v;
        float ksq = v * v;
        #pragma unroll
        for (int o = 16; o; o >>= 1) ksq += __shfl_xor_sync(0xffffffffu, ksq, o);
        if (lane == 0) red[wid] = ksq;
    } else if (tid == 64) {
        ps[0] = pp_sum(b, 64);
    }
    __syncthreads();
    const float beta  = softplusf(ps[0]);
    const float knorm = sqrtf(red[0] + red[1]);

    // producer: thread 255 (warp 7 -> its own tile last; no self-deadlock)
    if (tid == 255) {
        #pragma unroll
        for (int i = 0; i < 8; ++i) {
            int buf = i & 3;
            if (i >= 4) mbar_wait(mbar0 + 8u * (8 + buf), 0);
            uint32_t fb = mbar0 + 8u * i;
            mbar_expect_tx(fb, K2_TB);
            bulk_g2s(tiles_u + buf * K2_TB, mb + (size_t)i * 64 * Mn, K2_TB, fb);
        }
    }

    // consumer: warp wid -> tile wid; thread -> rows 2*lane, 2*lane+1
    mbar_wait(mbar0 + 8u * wid, 0);
    const float4* base = (const float4*)(tiles + (wid & 3) * 4096);
    const float4* va = base + lane * 32;
    const float4* vb = va + 16;
    const float4* k4 = (const float4*)k_sh;
    const int rot = lane & 15;
    float d0 = 0.f, q0 = 0.f, d1 = 0.f, q1 = 0.f;
    #pragma unroll 2
    for (int j = 0; j < 16; ++j) {
        int j0 = (j + rot) & 15;
        float4 kk = k4[j0];
        float4 v0 = va[j0];
        float4 v1 = vb[j0];
        d0 = fmaf(kk.x, v0.x, fmaf(kk.y, v0.y, fmaf(kk.z, v0.z, fmaf(kk.w, v0.w, d0))));
        q0 = fmaf(v0.x, v0.x, fmaf(v0.y, v0.y, fmaf(v0.z, v0.z, fmaf(v0.w, v0.w, q0))));
        d1 = fmaf(kk.x, v1.x, fmaf(kk.y, v1.y, fmaf(kk.z, v1.z, fmaf(kk.w, v1.w, d1))));
        q1 = fmaf(v1.x, v1.x, fmaf(v1.y, v1.y, fmaf(v1.z, v1.z, fmaf(v1.w, v1.w, q1))));
    }
    float z0 = beta * d0 / (knorm * sqrtf(q0) + EPSf);
    float z1 = beta * d1 / (knorm * sqrtf(q1) + EPSf);
    mbar_arrive(mbar0 + 8u * (8 + (wid & 3)));
    ((float2*)(g_z + (size_t)b * Nn + half * 512 + wid * 64))[lane] = make_float2(z0, z1);
}

// ===================== K34: softmax chain + weighted read (L2-hot per split) =======
__device__ __forceinline__ float block_sum512(float v, float* red, int lane, int wid) {
    #pragma unroll
    for (int o = 16; o; o >>= 1) v += __shfl_xor_sync(0xffffffffu, v, o);
    if (lane == 0) red[wid] = v;
    __syncthreads();
    if (wid == 0) {
        float x = (lane < 16) ? red[lane] : 0.0f;
        #pragma unroll
        for (int o = 8; o; o >>= 1) x += __shfl_xor_sync(0xffffffffu, x, o);
        if (lane == 0) red[16] = x;
    }
    __syncthreads();
    return red[16];
}

__global__ __launch_bounds__(512) void read_kernel(const float* __restrict__ w_prev,
                                                   const float* __restrict__ memory,
                                                   float* __restrict__ out_md,
                                                   float* __restrict__ out_w,
                                                   int base_b) {
    __shared__ float wg_sh[Nn];     // reused as partials [16][64] at the end
    __shared__ float w_sh[Nn];
    __shared__ float red[17];
    __shared__ float sc[5];         // g, s0, s1, s2, y
    const int b    = base_b + (BSPLIT - 1) - blockIdx.x;   // reverse within split
    const int tid  = threadIdx.x;
    const int lane = tid & 31;
    const int wid  = tid >> 5;
    const float* mb = memory + (size_t)b * Nn * Mn;

    if (tid == 0) {
        float p65 = pp_sum(b, 65);
        float a0  = pp_sum(b, 66), a1 = pp_sum(b, 67), a2 = pp_sum(b, 68);
        float p69 = pp_sum(b, 69);
        float mx = fmaxf(a0, fmaxf(a1, a2));
        float e0 = expf(a0 - mx), e1 = expf(a1 - mx), e2 = expf(a2 - mx);
        float dn = e0 + e1 + e2;
        sc[0] = 1.0f / (1.0f + expf(-p65));
        sc[1] = e0 / dn; sc[2] = e1 / dn; sc[3] = e2 / dn;
        sc[4] = 1.0f + softplusf(p69);
    }

    float2 z2 = ((const float2*)(g_z + (size_t)b * Nn))[tid];
    float2 wprev2 = ((const float2*)(w_prev + (size_t)b * Nn))[tid];

    float e0 = expf(z2.x), e1 = expf(z2.y);     // |z| <= beta, no max pass needed
    float denom = block_sum512(e0 + e1, red, lane, wid);   // sc visible after its syncs
    float inv_d = 1.0f / denom;
    const float gg = sc[0], s0 = sc[1], s1 = sc[2], s2 = sc[3], yy = sc[4];
    float omg = 1.0f - gg;
    float wg0 = fmaf(gg, e0 * inv_d, omg * wprev2.x);
    float wg1 = fmaf(gg, e1 * inv_d, omg * wprev2.y);
    wg_sh[2 * tid]     = wg0;
    wg_sh[2 * tid + 1] = wg1;
    __syncthreads();
    float wt0 = s0 * wg1 + s1 * wg0 + s2 * wg_sh[(2 * tid - 1) & (Nn - 1)];
    float wt1 = s0 * wg_sh[(2 * tid + 2) & (Nn - 1)] + s1 * wg1 + s2 * wg0;
    float wp0 = __powf(wt0, yy);
    float wp1 = __powf(wt1, yy);
    float psum = block_sum512(wp0 + wp1, red, lane, wid);
    float inv_p = 1.0f / (psum + EPSf);
    float wv0 = wp0 * inv_p, wv1 = wp1 * inv_p;
    w_sh[2 * tid]     = wv0;
    w_sh[2 * tid + 1] = wv1;
    ((float2*)(out_w + (size_t)b * Nn))[tid] = make_float2(wv0, wv1);
    __syncthreads();   // w_sh ready; wg_sh reads done -> reuse as partials

    const int sub  = lane & 15;
    const int half = lane >> 4;
    float4 acc = make_float4(0.f, 0.f, 0.f, 0.f);
    #pragma unroll 4
    for (int it = 0; it < 32; ++it) {
        int n = it * 32 + wid * 2 + half;
        float4 v = ((const float4*)(mb + (size_t)n * Mn))[sub];
        float wn = w_sh[n];
        acc.x = fmaf(wn, v.x, acc.x);
        acc.y = fmaf(wn, v.y, acc.y);
        acc.z = fmaf(wn, v.z, acc.z);
        acc.w = fmaf(wn, v.w, acc.w);
    }
    acc.x += __shfl_xor_sync(0xffffffffu, acc.x, 16);
    acc.y += __shfl_xor_sync(0xffffffffu, acc.y, 16);
    acc.z += __shfl_xor_sync(0xffffffffu, acc.z, 16);
    acc.w += __shfl_xor_sync(0xffffffffu, acc.w, 16);
    if (half == 0)
        ((float4*)wg_sh)[wid * 16 + sub] = acc;     // partials [16][64]
    __syncthreads();
    if (tid < Mn) {
        float s = 0.0f;
        #pragma unroll
        for (int w = 0; w < 16; ++w) s += wg_sh[w * 64 + tid];
        out_md[(size_t)b * Mn + tid] = s;
    }
}

extern "C" void kernel_launch(void* const* d_in, const int* in_sizes, int n_in,
                              void* d_out, int out_size) {
    const float* embeddings = (const float*)d_in[0];   // [1024, 512]
    const float* w_prev     = (const float*)d_in[1];   // [1024, 1024]
    const float* memory     = (const float*)d_in[2];   // [1024, 1024, 64]
    const float* W          = (const float*)d_in[3];   // [512, 70]
    const float* bias       = (const float*)d_in[4];   // [70]

    float* out_md = (float*)d_out;             // memory_data [1024, 64] first
    float* out_w  = out_md + (size_t)Bn * Mn;  // then w [1024, 1024]

    proj_kernel<<<1024, 576>>>(embeddings, W, bias);
    cudaFuncSetAttribute(sim_kernel, cudaFuncAttributeMaxDynamicSharedMemorySize, K2_SMEM_BYTES);
    for (int s = 0; s < NSPLIT; ++s) {
        sim_kernel<<<2 * BSPLIT, 256, K2_SMEM_BYTES>>>(memory, s * BSPLIT);
        read_kernel<<<BSPLIT, 512>>>(w_prev, memory, out_md, out_w, s * BSPLIT);
    }
}

// round 12
// speedup vs baseline: 1.0265x; 1.0265x over previous
#include <cuda_runtime.h>
#include <math.h>
#include <stdint.h>

#define Bn 1024
#define En 512
#define Nn 1024
#define Mn 64
#define Pn 70
#define EPSf 1e-16f

#define NSPLIT 4
#define BSPLIT (Bn / NSPLIT)      // 256
#define SIM_BLKS (BSPLIT * 4)     // 1024 sim CTAs per split (quarter rows each)
#define K_TB 16384                // 16KB tile = 64 rows

// smem: tiles 16384 floats | k 64 | red 2 | ps 1 | pad | 4 mbars
#define K_SMEM_BYTES ((16384 + 80) * 4 + 4 * 8 + 16)

// scratch: z[B,N]; proj partials g_pp[b][chunk8][72]
__device__ float g_z[Bn * Nn];
__device__ float g_pp[Bn * 8 * 72];

__device__ __forceinline__ float softplusf(float x) {
    return fmaxf(x, 0.0f) + log1pf(expf(-fabsf(x)));
}
__device__ __forceinline__ uint32_t s2u(const void* p) {
    return (uint32_t)__cvta_generic_to_shared(p);
}
__device__ __forceinline__ void mbar_init(uint32_t a, uint32_t cnt) {
    asm volatile("mbarrier.init.shared.b64 [%0], %1;" :: "r"(a), "r"(cnt) : "memory");
}
__device__ __forceinline__ void mbar_expect_tx(uint32_t a, uint32_t bytes) {
    asm volatile("mbarrier.arrive.expect_tx.shared.b64 _, [%0], %1;" :: "r"(a), "r"(bytes) : "memory");
}
__device__ __forceinline__ void bulk_g2s(uint32_t dst, const void* src, uint32_t bytes, uint32_t mbar) {
    asm volatile("cp.async.bulk.shared::cta.global.mbarrier::complete_tx::bytes [%0], [%1], %2, [%3];"
                 :: "r"(dst), "l"(src), "r"(bytes), "r"(mbar) : "memory");
}
__device__ __forceinline__ void mbar_wait(uint32_t a, uint32_t parity) {
    asm volatile(
        "{\n\t.reg .pred P;\n\t"
        "W0_%=:\n\t"
        "mbarrier.try_wait.parity.acquire.cta.shared::cta.b64 P, [%0], %1, 0x989680;\n\t"
        "@P bra.uni W1_%=;\n\t"
        "bra.uni W0_%=;\n\t"
        "W1_%=:\n\t}"
        :: "r"(a), "r"(parity) : "memory");
}

// ===================== K1: proj partials, 8-way split-K =====================
__global__ __launch_bounds__(576) void proj_kernel(const float* __restrict__ emb,
                                                   const float* __restrict__ W,
                                                   const float* __restrict__ bias) {
    __shared__ float W_sh[64 * Pn];
    __shared__ float e_sh[8 * 64];

    const int tid   = threadIdx.x;
    const int group = blockIdx.x >> 3;
    const int chunk = blockIdx.x & 7;
    const int b0    = group * 8;
    const int e0    = chunk * 64;

    {
        const float4* Wv = (const float4*)(W + (size_t)e0 * Pn);
        float4* Ws = (float4*)W_sh;
        #pragma unroll 2
        for (int i = tid; i < 64 * Pn / 4; i += 576) Ws[i] = Wv[i];
        if (tid < 128) {
            int r = tid >> 4, j = tid & 15;
            ((float4*)(e_sh + r * 64))[j] =
                ((const float4*)(emb + (size_t)(b0 + r) * En + e0))[j];
        }
    }
    __syncthreads();

    if (tid < 560) {
        const int r = tid / 70, c = tid - r * 70;
        const float* er = e_sh + r * 64;
        float a0 = 0.f, a1 = 0.f, a2 = 0.f, a3 = 0.f;
        #pragma unroll 8
        for (int e = 0; e < 64; e += 4) {
            float4 ev = *(const float4*)(er + e);
            a0 = fmaf(ev.x, W_sh[(e + 0) * Pn + c], a0);
            a1 = fmaf(ev.y, W_sh[(e + 1) * Pn + c], a1);
            a2 = fmaf(ev.z, W_sh[(e + 2) * Pn + c], a2);
            a3 = fmaf(ev.w, W_sh[(e + 3) * Pn + c], a3);
        }
        float acc = (a0 + a1) + (a2 + a3);
        if (chunk == 0) acc += bias[c];
        g_pp[((size_t)(b0 + r) * 8 + chunk) * 72 + c] = acc;
    }
}

__device__ __forceinline__ float pp_sum(int b, int i) {
    const float* p = g_pp + (size_t)b * 8 * 72 + i;
    float s = 0.f;
    #pragma unroll
    for (int c = 0; c < 8; ++c) s += p[c * 72];
    return s;
}

// ===================== sim body: CTA = 256 rows of one b, 4 tiles posted up-front ====
__device__ __forceinline__ void sim_body(const float* __restrict__ memory,
                                         int sim_base, int bx, float* smem) {
    float*    tiles = smem;                       // 16384
    float*    k_sh  = smem + 16384;               // 64
    float*    red   = k_sh + 64;                  // 2
    float*    ps    = red + 2;                    // 1
    uint64_t* mbars = (uint64_t*)(k_sh + 80);     // full[0..3] single-use

    const int b   = sim_base + (bx >> 2);
    const int q   = bx & 3;
    const int tid = threadIdx.x;
    const int lane = tid & 31;
    const int wid  = tid >> 5;                    // 0..7
    const float* mb = memory + ((size_t)b * Nn + q * 256) * Mn;

    const uint32_t tiles_u = s2u(tiles);
    const uint32_t mbar0   = s2u(mbars);

    if (tid == 0) {
        #pragma unroll
        for (int t = 0; t < 4; ++t) mbar_init(mbar0 + 8u * t, 1);
    }
    if (tid < 64) {
        float v = pp_sum(b, tid);
        k_sh[tid] = v;
        float ksq = v * v;
        #pragma unroll
        for (int o = 16; o; o >>= 1) ksq += __shfl_xor_sync(0xffffffffu, ksq, o);
        if (lane == 0) red[wid] = ksq;
    } else if (tid == 64) {
        ps[0] = pp_sum(b, 64);
    }
    __syncthreads();   // mbars visible + k/red/ps ready
    const float beta  = softplusf(ps[0]);
    const float knorm = sqrtf(red[0] + red[1]);

    // post all 4 tile loads immediately (no backpressure needed)
    if (tid == 0) {
        #pragma unroll
        for (int i = 0; i < 4; ++i) {
            uint32_t fb = mbar0 + 8u * i;
            mbar_expect_tx(fb, K_TB);
            bulk_g2s(tiles_u + i * K_TB, mb + (size_t)i * 64 * Mn, K_TB, fb);
        }
    }

    // consumer: warp pair (2w,2w+1) -> tile w; thread -> one row
    const int tile = wid >> 1;
    const int row  = (wid & 1) * 32 + lane;       // row within tile, 0..63
    mbar_wait(mbar0 + 8u * tile, 0);
    const float4* vrow = (const float4*)(tiles + tile * 4096 + row * 64);
    const float4* k4   = (const float4*)k_sh;
    const int rot = lane & 15;
    float d0 = 0.f, q0 = 0.f, d1 = 0.f, q1 = 0.f;
    #pragma unroll 4
    for (int j = 0; j < 16; j += 2) {
        int j0 = (j + rot) & 15;
        int j1 = (j + 1 + rot) & 15;
        float4 kk = k4[j0];  float4 v = vrow[j0];
        float4 kk2 = k4[j1]; float4 v2 = vrow[j1];
        d0 = fmaf(kk.x, v.x, fmaf(kk.y, v.y, fmaf(kk.z, v.z, fmaf(kk.w, v.w, d0))));
        q0 = fmaf(v.x, v.x, fmaf(v.y, v.y, fmaf(v.z, v.z, fmaf(v.w, v.w, q0))));
        d1 = fmaf(kk2.x, v2.x, fmaf(kk2.y, v2.y, fmaf(kk2.z, v2.z, fmaf(kk2.w, v2.w, d1))));
        q1 = fmaf(v2.x, v2.x, fmaf(v2.y, v2.y, fmaf(v2.z, v2.z, fmaf(v2.w, v2.w, q1))));
    }
    float z = beta * (d0 + d1) / (knorm * sqrtf(q0 + q1) + EPSf);
    g_z[(size_t)b * Nn + q * 256 + tile * 64 + row] = z;
}

// ===================== read body: 256 threads, 4 n per thread =====================
__device__ __forceinline__ float block_sum256(float v, float* red, int lane, int wid) {
    #pragma unroll
    for (int o = 16; o; o >>= 1) v += __shfl_xor_sync(0xffffffffu, v, o);
    if (lane == 0) red[wid] = v;
    __syncthreads();
    if (wid == 0) {
        float x = (lane < 8) ? red[lane] : 0.0f;
        #pragma unroll
        for (int o = 4; o; o >>= 1) x += __shfl_xor_sync(0xffffffffu, x, o);
        if (lane == 0) red[8] = x;
    }
    __syncthreads();
    return red[8];
}

__device__ __forceinline__ void read_body(const float* __restrict__ w_prev,
                                          const float* __restrict__ memory,
                                          float* __restrict__ out_md,
                                          float* __restrict__ out_w,
                                          int read_base, int rb, float* smem) {
    float* wg_sh = smem;            // 1024 ; reused as partials [8][64] in phase D
    float* w_sh  = smem + 1024;     // 1024
    float* red   = smem + 2048;     // 9
    float* sc    = smem + 2057;     // 5

    const int b    = read_base + (BSPLIT - 1) - rb;    // reverse within split
    const int tid  = threadIdx.x;
    const int lane = tid & 31;
    const int wid  = tid >> 5;      // 0..7
    const float* mb = memory + (size_t)b * Nn * Mn;

    if (tid == 0) {
        float p65 = pp_sum(b, 65);
        float a0  = pp_sum(b, 66), a1 = pp_sum(b, 67), a2 = pp_sum(b, 68);
        float p69 = pp_sum(b, 69);
        float mx = fmaxf(a0, fmaxf(a1, a2));
        float e0 = expf(a0 - mx), e1 = expf(a1 - mx), e2 = expf(a2 - mx);
        float dn = e0 + e1 + e2;
        sc[0] = 1.0f / (1.0f + expf(-p65));
        sc[1] = e0 / dn; sc[2] = e1 / dn; sc[3] = e2 / dn;
        sc[4] = 1.0f + softplusf(p69);
    }

    float4 z4 = ((const float4*)(g_z + (size_t)b * Nn))[tid];
    float4 wp4 = ((const float4*)(w_prev + (size_t)b * Nn))[tid];

    float e0 = expf(z4.x), e1 = expf(z4.y), e2 = expf(z4.z), e3 = expf(z4.w);
    float denom = block_sum256((e0 + e1) + (e2 + e3), red, lane, wid);  // sc visible after
    float inv_d = 1.0f / denom;
    const float gg = sc[0], s0 = sc[1], s1 = sc[2], s2 = sc[3], yy = sc[4];
    float omg = 1.0f - gg;
    float wg0 = fmaf(gg, e0 * inv_d, omg * wp4.x);
    float wg1 = fmaf(gg, e1 * inv_d, omg * wp4.y);
    float wg2 = fmaf(gg, e2 * inv_d, omg * wp4.z);
    float wg3 = fmaf(gg, e3 * inv_d, omg * wp4.w);
    ((float4*)wg_sh)[tid] = make_float4(wg0, wg1, wg2, wg3);
    __syncthreads();
    float prev = wg_sh[(4 * tid - 1) & (Nn - 1)];
    float next = wg_sh[(4 * tid + 4) & (Nn - 1)];
    float wt0 = s0 * wg1 + s1 * wg0 + s2 * prev;
    float wt1 = s0 * wg2 + s1 * wg1 + s2 * wg0;
    float wt2 = s0 * wg3 + s1 * wg2 + s2 * wg1;
    float wt3 = s0 * next + s1 * wg3 + s2 * wg2;
    float p0 = __powf(wt0, yy), p1 = __powf(wt1, yy);
    float p2 = __powf(wt2, yy), p3 = __powf(wt3, yy);
    float psum = block_sum256((p0 + p1) + (p2 + p3), red, lane, wid);
    float inv_p = 1.0f / (psum + EPSf);
    float wv0 = p0 * inv_p, wv1 = p1 * inv_p, wv2 = p2 * inv_p, wv3 = p3 * inv_p;
    ((float4*)w_sh)[tid] = make_float4(wv0, wv1, wv2, wv3);
    ((float4*)(out_w + (size_t)b * Nn))[tid] = make_float4(wv0, wv1, wv2, wv3);
    __syncthreads();   // w_sh ready; wg_sh reads done -> reuse as partials

    const int sub  = lane & 15;
    const int half = lane >> 4;
    float4 acc = make_float4(0.f, 0.f, 0.f, 0.f);
    #pragma unroll 4
    for (int it = 0; it < 64; ++it) {
        int n = it * 16 + wid * 2 + half;
        float4 v = ((const float4*)(mb + (size_t)n * Mn))[sub];
        float wn = w_sh[n];
        acc.x = fmaf(wn, v.x, acc.x);
        acc.y = fmaf(wn, v.y, acc.y);
        acc.z = fmaf(wn, v.z, acc.z);
        acc.w = fmaf(wn, v.w, acc.w);
    }
    acc.x += __shfl_xor_sync(0xffffffffu, acc.x, 16);
    acc.y += __shfl_xor_sync(0xffffffffu, acc.y, 16);
    acc.z += __shfl_xor_sync(0xffffffffu, acc.z, 16);
    acc.w += __shfl_xor_sync(0xffffffffu, acc.w, 16);
    if (half == 0)
        ((float4*)wg_sh)[wid * 16 + sub] = acc;     // partials [8][64]
    __syncthreads();
    if (tid < Mn) {
        float s = 0.0f;
        #pragma unroll
        for (int w = 0; w < 8; ++w) s += wg_sh[w * 64 + tid];
        out_md[(size_t)b * Mn + tid] = s;
    }
}

// ===================== fused launch: sim split s + read split s-1 =====================
__global__ __launch_bounds__(256) void fused_kernel(const float* __restrict__ memory,
                                                    const float* __restrict__ w_prev,
                                                    float* __restrict__ out_md,
                                                    float* __restrict__ out_w,
                                                    int sim_base, int read_base, int n_sim) {
    extern __shared__ float smem[];
    if ((int)blockIdx.x < n_sim)
        sim_body(memory, sim_base, blockIdx.x, smem);
    else
        read_body(w_prev, memory, out_md, out_w, read_base, blockIdx.x - n_sim, smem);
}

extern "C" void kernel_launch(void* const* d_in, const int* in_sizes, int n_in,
                              void* d_out, int out_size) {
    const float* embeddings = (const float*)d_in[0];   // [1024, 512]
    const float* w_prev     = (const float*)d_in[1];   // [1024, 1024]
    const float* memory     = (const float*)d_in[2];   // [1024, 1024, 64]
    const float* W          = (const float*)d_in[3];   // [512, 70]
    const float* bias       = (const float*)d_in[4];   // [70]

    float* out_md = (float*)d_out;             // memory_data [1024, 64] first
    float* out_w  = out_md + (size_t)Bn * Mn;  // then w [1024, 1024]

    proj_kernel<<<1024, 576>>>(embeddings, W, bias);
    cudaFuncSetAttribute(fused_kernel, cudaFuncAttributeMaxDynamicSharedMemorySize, K_SMEM_BYTES);

    // s=0: sim only
    fused_kernel<<<SIM_BLKS, 256, K_SMEM_BYTES>>>(memory, w_prev, out_md, out_w,
                                                  0, 0, SIM_BLKS);
    // s=1..3: sim split s + read split s-1 (read rides L2 residue + fills sim tail)
    for (int s = 1; s < NSPLIT; ++s)
        fused_kernel<<<SIM_BLKS + BSPLIT, 256, K_SMEM_BYTES>>>(memory, w_prev, out_md, out_w,
                                                               s * BSPLIT, (s - 1) * BSPLIT, SIM_BLKS);
    // final: read split 3 only
    fused_kernel<<<BSPLIT, 256, K_SMEM_BYTES>>>(memory, w_prev, out_md, out_w,
                                                0, (NSPLIT - 1) * BSPLIT, 0);
}

// round 13
// speedup vs baseline: 1.7994x; 1.7529x over previous
#include <cuda_runtime.h>
#include <math.h>
#include <stdint.h>

#define Bn 1024
#define En 512
#define Nn 1024
#define Mn 64
#define Pn 70
#define EPSf 1e-16f

// scratch: z[B,N]; proj partials g_pp[b][chunk8][72]; per-b finish counter
__device__ float g_z[Bn * Nn];
__device__ float g_pp[Bn * 8 * 72];
__device__ int   g_cnt[Bn];

__device__ __forceinline__ float softplusf(float x) {
    return fmaxf(x, 0.0f) + log1pf(expf(-fabsf(x)));
}
__device__ __forceinline__ uint32_t s2u(const void* p) {
    return (uint32_t)__cvta_generic_to_shared(p);
}
__device__ __forceinline__ void mbar_init(uint32_t a, uint32_t cnt) {
    asm volatile("mbarrier.init.shared.b64 [%0], %1;" :: "r"(a), "r"(cnt) : "memory");
}
__device__ __forceinline__ void mbar_expect_tx(uint32_t a, uint32_t bytes) {
    asm volatile("mbarrier.arrive.expect_tx.shared.b64 _, [%0], %1;" :: "r"(a), "r"(bytes) : "memory");
}
__device__ __forceinline__ void mbar_arrive(uint32_t a) {
    asm volatile("mbarrier.arrive.shared.b64 _, [%0];" :: "r"(a) : "memory");
}
__device__ __forceinline__ void bulk_g2s(uint32_t dst, const void* src, uint32_t bytes, uint32_t mbar) {
    asm volatile("cp.async.bulk.shared::cta.global.mbarrier::complete_tx::bytes [%0], [%1], %2, [%3];"
                 :: "r"(dst), "l"(src), "r"(bytes), "r"(mbar) : "memory");
}
__device__ __forceinline__ void mbar_wait(uint32_t a, uint32_t parity) {
    asm volatile(
        "{\n\t.reg .pred P;\n\t"
        "W0_%=:\n\t"
        "mbarrier.try_wait.parity.acquire.cta.shared::cta.b64 P, [%0], %1, 0x989680;\n\t"
        "@P bra.uni W1_%=;\n\t"
        "bra.uni W0_%=;\n\t"
        "W1_%=:\n\t}"
        :: "r"(a), "r"(parity) : "memory");
}

// ===================== K1: proj partials, 8-way split-K + counter reset ============
__global__ __launch_bounds__(576) void proj_kernel(const float* __restrict__ emb,
                                                   const float* __restrict__ W,
                                                   const float* __restrict__ bias) {
    __shared__ float W_sh[64 * Pn];
    __shared__ float e_sh[8 * 64];

    const int tid   = threadIdx.x;
    const int group = blockIdx.x >> 3;
    const int chunk = blockIdx.x & 7;
    const int b0    = group * 8;
    const int e0    = chunk * 64;

    if (chunk == 0 && tid < 8) g_cnt[b0 + tid] = 0;   // reset handoff counters

    {
        const float4* Wv = (const float4*)(W + (size_t)e0 * Pn);
        float4* Ws = (float4*)W_sh;
        #pragma unroll 2
        for (int i = tid; i < 64 * Pn / 4; i += 576) Ws[i] = Wv[i];
        if (tid < 128) {
            int r = tid >> 4, j = tid & 15;
            ((float4*)(e_sh + r * 64))[j] =
                ((const float4*)(emb + (size_t)(b0 + r) * En + e0))[j];
        }
    }
    __syncthreads();

    if (tid < 560) {
        const int r = tid / 70, c = tid - r * 70;
        const float* er = e_sh + r * 64;
        float a0 = 0.f, a1 = 0.f, a2 = 0.f, a3 = 0.f;
        #pragma unroll 8
        for (int e = 0; e < 64; e += 4) {
            float4 ev = *(const float4*)(er + e);
            a0 = fmaf(ev.x, W_sh[(e + 0) * Pn + c], a0);
            a1 = fmaf(ev.y, W_sh[(e + 1) * Pn + c], a1);
            a2 = fmaf(ev.z, W_sh[(e + 2) * Pn + c], a2);
            a3 = fmaf(ev.w, W_sh[(e + 3) * Pn + c], a3);
        }
        float acc = (a0 + a1) + (a2 + a3);
        if (chunk == 0) acc += bias[c];
        g_pp[((size_t)(b0 + r) * 8 + chunk) * 72 + c] = acc;
    }
}

__device__ __forceinline__ float pp_sum(int b, int i) {
    const float* p = g_pp + (size_t)b * 8 * 72 + i;
    float s = 0.f;
    #pragma unroll
    for (int c = 0; c < 8; ++c) s += p[c * 72];
    return s;
}

// ===================== fused sim + last-finisher read =====================
// smem: tiles 16384 | k 64 | red 2 | ps 1 | flag | pad to 80 | 12 mbars
#define K2_SMEM_BYTES ((16384 + 80) * 4 + 12 * 8 + 16)

__device__ __forceinline__ float block_sum256(float v, float* red, int lane, int wid) {
    #pragma unroll
    for (int o = 16; o; o >>= 1) v += __shfl_xor_sync(0xffffffffu, v, o);
    if (lane == 0) red[wid] = v;
    __syncthreads();
    if (wid == 0) {
        float x = (lane < 8) ? red[lane] : 0.0f;
        #pragma unroll
        for (int o = 4; o; o >>= 1) x += __shfl_xor_sync(0xffffffffu, x, o);
        if (lane == 0) red[8] = x;
    }
    __syncthreads();
    return red[8];
}

__global__ __launch_bounds__(256) void fused_kernel(const float* __restrict__ memory,
                                                    const float* __restrict__ w_prev,
                                                    float* __restrict__ out_md,
                                                    float* __restrict__ out_w) {
    extern __shared__ float smem[];
    float*    tiles = smem;                       // 16384 (4 x 16KB bufs)
    float*    k_sh  = smem + 16384;               // 64
    float*    redp  = k_sh + 64;                  // 2
    float*    ps    = redp + 2;                   // 1
    int*      flag  = (int*)(redp + 3);           // 1
    uint64_t* mbars = (uint64_t*)(k_sh + 80);     // full[0..7], empty[8..11]

    const int b    = blockIdx.x >> 1;
    const int half = blockIdx.x & 1;
    const int tid  = threadIdx.x;
    const int lane = tid & 31;
    const int wid  = tid >> 5;
    const float* mb = memory + ((size_t)b * Nn + half * 512) * Mn;

    const uint32_t tiles_u = s2u(tiles);
    const uint32_t mbar0   = s2u(mbars);

    if (tid == 0) {
        #pragma unroll
        for (int t = 0; t < 8; ++t) mbar_init(mbar0 + 8u * t, 1);
        #pragma unroll
        for (int k = 0; k < 4; ++k) mbar_init(mbar0 + 8u * (8 + k), 32);
    }
    if (tid < 64) {
        float v = pp_sum(b, tid);
        k_sh[tid] = v;
        float ksq = v * v;
        #pragma unroll
        for (int o = 16; o; o >>= 1) ksq += __shfl_xor_sync(0xffffffffu, ksq, o);
        if (lane == 0) redp[wid] = ksq;
    } else if (tid == 64) {
        ps[0] = pp_sum(b, 64);
    }
    __syncthreads();
    const float beta  = softplusf(ps[0]);
    const float knorm = sqrtf(redp[0] + redp[1]);

    // producer: thread 255 (warp 7 -> its own tile last; no self-deadlock)
    if (tid == 255) {
        #pragma unroll
        for (int i = 0; i < 8; ++i) {
            int buf = i & 3;
            if (i >= 4) mbar_wait(mbar0 + 8u * (8 + buf), 0);
            uint32_t fb = mbar0 + 8u * i;
            mbar_expect_tx(fb, 16384);
            bulk_g2s(tiles_u + buf * 16384, mb + (size_t)i * 64 * Mn, 16384, fb);
        }
    }

    // consumer: warp wid -> tile wid; thread -> rows 2*lane, 2*lane+1
    {
        mbar_wait(mbar0 + 8u * wid, 0);
        const float4* va = (const float4*)(tiles + (wid & 3) * 4096) + lane * 32;
        const float4* vb = va + 16;
        const float4* k4 = (const float4*)k_sh;
        const int rot = lane & 15;
        float d0 = 0.f, q0 = 0.f, d1 = 0.f, q1 = 0.f;
        #pragma unroll 2
        for (int j = 0; j < 16; ++j) {
            int j0 = (j + rot) & 15;
            float4 kk = k4[j0];
            float4 v0 = va[j0];
            float4 v1 = vb[j0];
            d0 = fmaf(kk.x, v0.x, fmaf(kk.y, v0.y, fmaf(kk.z, v0.z, fmaf(kk.w, v0.w, d0))));
            q0 = fmaf(v0.x, v0.x, fmaf(v0.y, v0.y, fmaf(v0.z, v0.z, fmaf(v0.w, v0.w, q0))));
            d1 = fmaf(kk.x, v1.x, fmaf(kk.y, v1.y, fmaf(kk.z, v1.z, fmaf(kk.w, v1.w, d1))));
            q1 = fmaf(v1.x, v1.x, fmaf(v1.y, v1.y, fmaf(v1.z, v1.z, fmaf(v1.w, v1.w, q1))));
        }
        float z0 = beta * d0 / (knorm * sqrtf(q0) + EPSf);
        float z1 = beta * d1 / (knorm * sqrtf(q1) + EPSf);
        mbar_arrive(mbar0 + 8u * (8 + (wid & 3)));
        ((float2*)(g_z + (size_t)b * Nn + half * 512 + wid * 64))[lane] = make_float2(z0, z1);
    }

    // ---- last-finisher handoff ----
    __threadfence();            // publish this CTA's z writes
    __syncthreads();
    if (tid == 0) {
        int old = atomicAdd(&g_cnt[b], 1);
        *flag = old;            // old==1 -> we are the second (last) finisher
    }
    __syncthreads();
    if (*flag != 1) return;     // first finisher exits; its sibling does the read
    __threadfence();            // acquire sibling's z writes

    // ================= read phase for b (memory[b] is L2-hot) =================
    float* wg_sh = tiles;           // 1024
    float* w_sh  = tiles + 1024;    // 1024
    float* red2  = tiles + 2048;    // 9
    float* sc    = tiles + 2064;    // 5
    const float* mbf = memory + (size_t)b * Nn * Mn;

    if (tid == 0) {
        float p65 = pp_sum(b, 65);
        float a0  = pp_sum(b, 66), a1 = pp_sum(b, 67), a2 = pp_sum(b, 68);
        float p69 = pp_sum(b, 69);
        float mx = fmaxf(a0, fmaxf(a1, a2));
        float e0 = expf(a0 - mx), e1 = expf(a1 - mx), e2 = expf(a2 - mx);
        float dn = e0 + e1 + e2;
        sc[0] = 1.0f / (1.0f + expf(-p65));
        sc[1] = e0 / dn; sc[2] = e1 / dn; sc[3] = e2 / dn;
        sc[4] = 1.0f + softplusf(p69);
    }

    float4 z4  = ((const float4*)(g_z + (size_t)b * Nn))[tid];
    float4 wp4 = ((const float4*)(w_prev + (size_t)b * Nn))[tid];

    float e0 = expf(z4.x), e1 = expf(z4.y), e2 = expf(z4.z), e3 = expf(z4.w);
    float denom = block_sum256((e0 + e1) + (e2 + e3), red2, lane, wid);  // sc visible after
    float inv_d = 1.0f / denom;
    const float gg = sc[0], s0 = sc[1], s1 = sc[2], s2 = sc[3], yy = sc[4];
    float omg = 1.0f - gg;
    float wg0 = fmaf(gg, e0 * inv_d, omg * wp4.x);
    float wg1 = fmaf(gg, e1 * inv_d, omg * wp4.y);
    float wg2 = fmaf(gg, e2 * inv_d, omg * wp4.z);
    float wg3 = fmaf(gg, e3 * inv_d, omg * wp4.w);
    ((float4*)wg_sh)[tid] = make_float4(wg0, wg1, wg2, wg3);
    __syncthreads();
    float prev = wg_sh[(4 * tid - 1) & (Nn - 1)];
    float next = wg_sh[(4 * tid + 4) & (Nn - 1)];
    float wt0 = s0 * wg1 + s1 * wg0 + s2 * prev;
    float wt1 = s0 * wg2 + s1 * wg1 + s2 * wg0;
    float wt2 = s0 * wg3 + s1 * wg2 + s2 * wg1;
    float wt3 = s0 * next + s1 * wg3 + s2 * wg2;
    float p0 = __powf(wt0, yy), p1 = __powf(wt1, yy);
    float p2 = __powf(wt2, yy), p3 = __powf(wt3, yy);
    float psum = block_sum256((p0 + p1) + (p2 + p3), red2, lane, wid);
    float inv_p = 1.0f / (psum + EPSf);
    float wv0 = p0 * inv_p, wv1 = p1 * inv_p, wv2 = p2 * inv_p, wv3 = p3 * inv_p;
    ((float4*)w_sh)[tid] = make_float4(wv0, wv1, wv2, wv3);
    ((float4*)(out_w + (size_t)b * Nn))[tid] = make_float4(wv0, wv1, wv2, wv3);
    __syncthreads();

    // weighted sum over all 1024 rows (mostly L2 hits)
    const int sub  = lane & 15;
    const int hh   = lane >> 4;
    float4 acc = make_float4(0.f, 0.f, 0.f, 0.f);
    #pragma unroll 4
    for (int it = 0; it < 64; ++it) {
        int n = it * 16 + wid * 2 + hh;
        float4 v = ((const float4*)(mbf + (size_t)n * Mn))[sub];
        float wn = w_sh[n];
        acc.x = fmaf(wn, v.x, acc.x);
        acc.y = fmaf(wn, v.y, acc.y);
        acc.z = fmaf(wn, v.z, acc.z);
        acc.w = fmaf(wn, v.w, acc.w);
    }
    acc.x += __shfl_xor_sync(0xffffffffu, acc.x, 16);
    acc.y += __shfl_xor_sync(0xffffffffu, acc.y, 16);
    acc.z += __shfl_xor_sync(0xffffffffu, acc.z, 16);
    acc.w += __shfl_xor_sync(0xffffffffu, acc.w, 16);
    __syncthreads();            // wg_sh shift-reads done before overwrite
    if (hh == 0)
        ((float4*)wg_sh)[wid * 16 + sub] = acc;     // partials [8][64]
    __syncthreads();
    if (tid < Mn) {
        float s = 0.0f;
        #pragma unroll
        for (int w = 0; w < 8; ++w) s += wg_sh[w * 64 + tid];
        out_md[(size_t)b * Mn + tid] = s;
    }
}

extern "C" void kernel_launch(void* const* d_in, const int* in_sizes, int n_in,
                              void* d_out, int out_size) {
    const float* embeddings = (const float*)d_in[0];   // [1024, 512]
    const float* w_prev     = (const float*)d_in[1];   // [1024, 1024]
    const float* memory     = (const float*)d_in[2];   // [1024, 1024, 64]
    const float* W          = (const float*)d_in[3];   // [512, 70]
    const float* bias       = (const float*)d_in[4];   // [70]

    float* out_md = (float*)d_out;             // memory_data [1024, 64] first
    float* out_w  = out_md + (size_t)Bn * Mn;  // then w [1024, 1024]

    proj_kernel<<<1024, 576>>>(embeddings, W, bias);
    cudaFuncSetAttribute(fused_kernel, cudaFuncAttributeMaxDynamicSharedMemorySize, K2_SMEM_BYTES);
    fused_kernel<<<2 * Bn, 256, K2_SMEM_BYTES>>>(memory, w_prev, out_md, out_w);
}